// round 9
// baseline (speedup 1.0000x reference)
#include <cuda_runtime.h>
#include <cuda_bf16.h>

#define N_CLASSES 26
#define IMG 68
#define BATCH 8192
#define NEXP 64
#define FC1N 500
#define FLATN 1960

// scratch (device globals; no allocation allowed)
__device__ __align__(16) float g_p1[N_CLASSES * 5 * 32 * 32];
__device__ __align__(16) float g_hcls[N_CLASSES * FLATN];
__device__ __align__(16) float g_u[N_CLASSES * FC1N];
__device__ __align__(16) float2 g_wx[FC1N];
__device__ __align__(16) float g_w2t[FC1N * NEXP];   // [k][e]

// ---------------------------------------------------------------------------
// Kernel A1: conv1 (5x5, 1->5) + relu + maxpool2 per (class, channel).
// Side work: transpose fc2_w -> g_w2t, extract fc1_w x-columns -> g_wx.
// grid = 130, block = 512.
// ---------------------------------------------------------------------------
__global__ void conv1_kernel(const float* __restrict__ images,
                             const float* __restrict__ w1,
                             const float* __restrict__ b1,
                             const float* __restrict__ fc1_w,
                             const float* __restrict__ fc2_w) {
    __shared__ float s_img[IMG * IMG];
    __shared__ float s_w[25];
    int c = blockIdx.x / 5, ch = blockIdx.x % 5;
    int tid = threadIdx.x;

    int gt = blockIdx.x * 512 + tid;
    if (gt < NEXP * FC1N) {
        int e = gt / FC1N, k = gt - e * FC1N;
        g_w2t[k * NEXP + e] = fc2_w[gt];
    }
    if (gt < FC1N) {
        float2 v;
        v.x = fc1_w[gt * 1962 + 1960];
        v.y = fc1_w[gt * 1962 + 1961];
        g_wx[gt] = v;
    }

    const float* img = images + c * IMG * IMG;
    for (int i = tid; i < IMG * IMG; i += 512) s_img[i] = img[i];
    if (tid < 25) s_w[tid] = w1[ch * 25 + tid];
    __syncthreads();
    float bb = b1[ch];
    float wr[25];
#pragma unroll
    for (int i = 0; i < 25; i++) wr[i] = s_w[i];
    float* outp = g_p1 + (c * 5 + ch) * 1024;
    for (int i = tid; i < 1024; i += 512) {
        int oy = i >> 5, ox = i & 31;
        int y0 = 2 * oy, x0 = 2 * ox;
        float p[6][6];
#pragma unroll
        for (int r = 0; r < 6; r++)
#pragma unroll
            for (int cc = 0; cc < 6; cc++) p[r][cc] = s_img[(y0 + r) * IMG + x0 + cc];
        float a00 = bb, a01 = bb, a10 = bb, a11 = bb;
#pragma unroll
        for (int ky = 0; ky < 5; ky++)
#pragma unroll
            for (int kx = 0; kx < 5; kx++) {
                float w = wr[ky * 5 + kx];
                a00 = fmaf(p[ky][kx], w, a00);
                a01 = fmaf(p[ky][kx + 1], w, a01);
                a10 = fmaf(p[ky + 1][kx], w, a10);
                a11 = fmaf(p[ky + 1][kx + 1], w, a11);
            }
        outp[i] = fmaxf(fmaxf(fmaxf(a00, a01), fmaxf(a10, a11)), 0.f);
    }
}

// ---------------------------------------------------------------------------
// Kernel A2: conv2 (5x5, 5->10) + relu + maxpool2. grid = 260, block = 256.
// ---------------------------------------------------------------------------
__global__ void conv2_kernel(const float* __restrict__ w2,
                             const float* __restrict__ b2) {
    __shared__ float s_p1[5 * 1024];
    __shared__ float s_w[125];
    int c = blockIdx.x / 10, co = blockIdx.x % 10;
    int tid = threadIdx.x;
    for (int i = tid; i < 5120; i += 256) s_p1[i] = g_p1[c * 5120 + i];
    if (tid < 125) s_w[tid] = w2[co * 125 + tid];
    __syncthreads();
    float bb = b2[co];
    for (int i = tid; i < 196; i += 256) {
        int oy = i / 14, ox = i % 14;
        int y0 = 2 * oy, x0 = 2 * ox;
        float a00 = bb, a01 = bb, a10 = bb, a11 = bb;
#pragma unroll
        for (int ci = 0; ci < 5; ci++) {
            const float* base = s_p1 + ci * 1024 + y0 * 32 + x0;
            float p[6][6];
#pragma unroll
            for (int r = 0; r < 6; r++)
#pragma unroll
                for (int cc = 0; cc < 6; cc++) p[r][cc] = base[r * 32 + cc];
            const float* wb = s_w + ci * 25;
#pragma unroll
            for (int ky = 0; ky < 5; ky++)
#pragma unroll
                for (int kx = 0; kx < 5; kx++) {
                    float w = wb[ky * 5 + kx];
                    a00 = fmaf(p[ky][kx], w, a00);
                    a01 = fmaf(p[ky][kx + 1], w, a01);
                    a10 = fmaf(p[ky + 1][kx], w, a10);
                    a11 = fmaf(p[ky + 1][kx + 1], w, a11);
                }
        }
        g_hcls[c * FLATN + co * 196 + i] =
            fmaxf(fmaxf(fmaxf(a00, a01), fmaxf(a10, a11)), 0.f);
    }
}

// ---------------------------------------------------------------------------
// Kernel B: fc1, single kernel. grid = 128, block = 256. (unchanged)
// ---------------------------------------------------------------------------
#define WROWP 1964
#define FC1SMEM ((16 * WROWP + 8 * WROWP + 1024) * 4)
__global__ void __launch_bounds__(256, 1) fc1_kernel(const float* __restrict__ fc1_w,
                                                     const float* __restrict__ fc1_b) {
    extern __shared__ float sm[];
    float* smW = sm;                    // [16][1964]
    float* smH = smW + 16 * WROWP;      // [8][1964]
    float* pbuf = smH + 8 * WROWP;      // [1024]
    int tid = threadIdx.x;
    int ot = blockIdx.x & 31, ct = blockIdx.x >> 5;

    for (int idx = tid; idx < 16 * 980; idx += 256) {
        int r = idx / 980, k2 = idx - r * 980;
        int row = ot * 16 + r;
        float2 v = (row < FC1N)
                       ? ((const float2*)(fc1_w + (long)row * 1962))[k2]
                       : make_float2(0.f, 0.f);
        *(float2*)(smW + r * WROWP + 2 * k2) = v;
    }
    for (int idx = tid; idx < 8 * 490; idx += 256) {
        int r = idx / 490, q = idx - r * 490;
        int ci = ct * 8 + r;
        float4 v = (ci < N_CLASSES)
                       ? ((const float4*)(g_hcls + ci * FLATN))[q]
                       : make_float4(0.f, 0.f, 0.f, 0.f);
        *(float4*)(smH + r * WROWP + 4 * q) = v;
    }
    __syncthreads();

    int o = tid & 15, cg = (tid >> 4) & 1, kq8 = tid >> 5;
    const float4* wq = (const float4*)(smW + o * WROWP);
    const float4* h0 = (const float4*)(smH + (4 * cg + 0) * WROWP);
    const float4* h1 = (const float4*)(smH + (4 * cg + 1) * WROWP);
    const float4* h2 = (const float4*)(smH + (4 * cg + 2) * WROWP);
    const float4* h3 = (const float4*)(smH + (4 * cg + 3) * WROWP);
    float a0 = 0.f, a1 = 0.f, a2 = 0.f, a3 = 0.f;
    for (int q = kq8; q < 490; q += 8) {
        float4 w = wq[q];
        float4 v0 = h0[q], v1 = h1[q], v2 = h2[q], v3 = h3[q];
        a0 = fmaf(w.x, v0.x, a0); a0 = fmaf(w.y, v0.y, a0);
        a0 = fmaf(w.z, v0.z, a0); a0 = fmaf(w.w, v0.w, a0);
        a1 = fmaf(w.x, v1.x, a1); a1 = fmaf(w.y, v1.y, a1);
        a1 = fmaf(w.z, v1.z, a1); a1 = fmaf(w.w, v1.w, a1);
        a2 = fmaf(w.x, v2.x, a2); a2 = fmaf(w.y, v2.y, a2);
        a2 = fmaf(w.z, v2.z, a2); a2 = fmaf(w.w, v2.w, a2);
        a3 = fmaf(w.x, v3.x, a3); a3 = fmaf(w.y, v3.y, a3);
        a3 = fmaf(w.z, v3.z, a3); a3 = fmaf(w.w, v3.w, a3);
    }
    pbuf[o + 16 * (4 * cg + 0) + 128 * kq8] = a0;
    pbuf[o + 16 * (4 * cg + 1) + 128 * kq8] = a1;
    pbuf[o + 16 * (4 * cg + 2) + 128 * kq8] = a2;
    pbuf[o + 16 * (4 * cg + 3) + 128 * kq8] = a3;
    __syncthreads();
    if (tid < 128) {
        int oo = tid & 15, c = tid >> 4;
        float s = 0.f;
#pragma unroll
        for (int j = 0; j < 8; j++) s += pbuf[oo + 16 * c + 128 * j];
        int cls = ct * 8 + c;
        int out = ot * 16 + oo;
        if (cls < N_CLASSES && out < FC1N)
            g_u[cls * FC1N + out] = s + fc1_b[out];
    }
}

// ---------------------------------------------------------------------------
// Kernel C: fused MoE. grid = 128, block = 1024 (32 warps = 8/SMSP).
// K split across two 512-thread teams (team t: k in [250t, 250t+250)).
// Thread tile 2s x 4e, acc packed over EXPERT pairs; w via LDG.128 from
// g_w2t (L1-resident); h via LDS.64 from full-K hs (132 KB smem).
// Team partials reduced through smem; CORRECTED Ls unpack ordering.
// ---------------------------------------------------------------------------
#define TS 64
#define KTOT 500
#define KHALF 250
#define HR 66      // hs row stride
#define LR 68
#define SMEMC ((KTOT * HR + TS * LR + 256 + 64 * 5 + 64) * 4)

#define FFMA2X(acc, hh, ww) \
    asm("fma.rn.f32x2 %0, %1, %2, %0;" : "+l"(acc) : "l"(hh), "l"(ww))

__global__ void __launch_bounds__(1024, 1)
moe_kernel(const float* __restrict__ x, const int* __restrict__ cls_idx,
           const float* __restrict__ fc2_b,
           const float* __restrict__ A_B, const float* __restrict__ A_C,
           const float* __restrict__ x_tar, float* __restrict__ out) {
    extern __shared__ float sm[];
    float* hs = sm;                       // [500][66] full K
    float* Ls = hs + KTOT * HR;           // [64][68]
    float* Gs = Ls + TS * LR;             // [64][4]
    float* b2s = Gs + 256;
    float* sx0 = b2s + 64;
    float* sx1 = sx0 + 64;
    float* sd0 = sx1 + 64;
    float* sd1 = sd0 + 64;
    int* scls = (int*)(sd1 + 64);

    int tid = threadIdx.x, lane = tid & 31, warp = tid >> 5;  // 32 warps
    int base = blockIdx.x * TS;

    if (tid < 256) Gs[tid] = A_B[tid] + A_C[tid];
    if (tid < 64) b2s[tid] = fc2_b[tid];
    if (tid < TS) {
        int s = base + tid;
        float x0v = x[2 * s], x1v = x[2 * s + 1];
        sx0[tid] = x0v; sx1[tid] = x1v;
        sd0[tid] = x_tar[0] - x0v;
        sd1[tid] = x_tar[1] - x1v;
        scls[tid] = cls_idx[s];
    }
    __syncthreads();

    // fill hs for ALL 500 k: 32 warps, warp-per-sample (2 rounds)
    for (int s = warp; s < TS; s += 32) {
        int cls = scls[s];
        float xx0 = sx0[s], xx1 = sx1[s];
        const float* urow = g_u + cls * FC1N;
        for (int k = lane; k < KTOT; k += 32) {
            float2 wv = g_wx[k];
            float v = fmaf(xx0, wv.x, fmaf(xx1, wv.y, urow[k]));
            hs[k * HR + s] = fmaxf(v, 0.f);
        }
    }
    __syncthreads();

    int team = tid >> 9;
    int r = tid & 511;
    int rlane = r & 31, rwarp = r >> 5;
    int eg = rlane & 1, sg = rlane >> 1;
    int sblk = rwarp & 1, eblk = rwarp >> 1;
    int s0 = 32 * sblk + 2 * sg;
    int e0 = 8 * eblk + 4 * eg;
    int kb = team * KHALF;

    // A00=(s0:e0,e0+1) A01=(s0:e0+2,e0+3) A10=(s1:e0,e0+1) A11=(s1:e0+2,e0+3)
    unsigned long long A00 = 0ull, A01 = 0ull, A10 = 0ull, A11 = 0ull;
    const float* hp = hs + kb * HR + s0;
    const float* wrow = g_w2t + kb * NEXP + e0;

#pragma unroll 4
    for (int k = 0; k < KHALF; k++) {
        float2 hv = *(const float2*)(hp + k * HR);
        ulonglong2 wv = *(const ulonglong2*)(wrow + k * NEXP);
        unsigned long long hd0, hd1;
        asm("mov.b64 %0, {%1,%1};" : "=l"(hd0) : "f"(hv.x));
        asm("mov.b64 %0, {%1,%1};" : "=l"(hd1) : "f"(hv.y));
        FFMA2X(A00, hd0, wv.x);
        FFMA2X(A01, hd0, wv.y);
        FFMA2X(A10, hd1, wv.x);
        FFMA2X(A11, hd1, wv.y);
    }
    __syncthreads();  // all hs reads done; hs space reusable for reduction

    // team 1 dumps partials into (reused) hs; team 0 accumulates + writes Ls
    unsigned long long* red = (unsigned long long*)hs;  // [512][4]
    if (team == 1) {
        unsigned long long* p = red + r * 4;
        p[0] = A00; p[1] = A01; p[2] = A10; p[3] = A11;
    }
    __syncthreads();
    if (team == 0) {
        const unsigned long long* p = red + r * 4;
        asm("add.rn.f32x2 %0, %0, %1;" : "+l"(A00) : "l"(p[0]));
        asm("add.rn.f32x2 %0, %0, %1;" : "+l"(A01) : "l"(p[1]));
        asm("add.rn.f32x2 %0, %0, %1;" : "+l"(A10) : "l"(p[2]));
        asm("add.rn.f32x2 %0, %0, %1;" : "+l"(A11) : "l"(p[3]));
        float t0, t1, t2, t3, u0, u1, u2, u3;
        asm("mov.b64 {%0,%1}, %2;" : "=f"(t0), "=f"(t1) : "l"(A00));
        asm("mov.b64 {%0,%1}, %2;" : "=f"(t2), "=f"(t3) : "l"(A01));
        asm("mov.b64 {%0,%1}, %2;" : "=f"(u0), "=f"(u1) : "l"(A10));
        asm("mov.b64 {%0,%1}, %2;" : "=f"(u2), "=f"(u3) : "l"(A11));
        float b0 = b2s[e0], b1 = b2s[e0 + 1], b2 = b2s[e0 + 2], b3 = b2s[e0 + 3];
        float* L0 = Ls + s0 * LR + e0;   // sample s0
        float* L1 = L0 + LR;             // sample s0+1
        L0[0] = t0 + b0; L0[1] = t1 + b1; L0[2] = t2 + b2; L0[3] = t3 + b3;
        L1[0] = u0 + b0; L1[1] = u1 + b1; L1[2] = u2 + b2; L1[3] = u3 + b3;
    }
    __syncthreads();

    // softmax over 64 + expert mix; warp-per-sample (2 rounds over 32 warps)
    for (int s = warp; s < TS; s += 32) {
        float l0 = Ls[s * LR + lane];
        float l1 = Ls[s * LR + 32 + lane];
        float m = fmaxf(l0, l1);
#pragma unroll
        for (int off = 16; off; off >>= 1) m = fmaxf(m, __shfl_xor_sync(~0u, m, off));
        float ee0 = __expf(l0 - m), ee1 = __expf(l1 - m);
        float d0 = sd0[s], d1 = sd1[s];
        const float* G0 = Gs + lane * 4;
        const float* G1 = Gs + (lane + 32) * 4;
        float y0 = ee0 * (G0[0] * d0 + G0[1] * d1) + ee1 * (G1[0] * d0 + G1[1] * d1);
        float y1 = ee0 * (G0[2] * d0 + G0[3] * d1) + ee1 * (G1[2] * d0 + G1[3] * d1);
        float Z = ee0 + ee1;
#pragma unroll
        for (int off = 16; off; off >>= 1) {
            y0 += __shfl_xor_sync(~0u, y0, off);
            y1 += __shfl_xor_sync(~0u, y1, off);
            Z += __shfl_xor_sync(~0u, Z, off);
        }
        if (lane == 0) {
            float inv = 1.f / Z;
            out[2 * (base + s) + 0] = y0 * inv;
            out[2 * (base + s) + 1] = y1 * inv;
        }
    }
}

// ---------------------------------------------------------------------------
extern "C" void kernel_launch(void* const* d_in, const int* in_sizes, int n_in,
                              void* d_out, int out_size) {
    const float* x       = (const float*)d_in[0];
    const int*   cls     = (const int*)d_in[1];
    const float* images  = (const float*)d_in[2];
    const float* conv1_w = (const float*)d_in[3];
    const float* conv1_b = (const float*)d_in[4];
    const float* conv2_w = (const float*)d_in[5];
    const float* conv2_b = (const float*)d_in[6];
    const float* fc1_w   = (const float*)d_in[7];
    const float* fc1_b   = (const float*)d_in[8];
    const float* fc2_w   = (const float*)d_in[9];
    const float* fc2_b   = (const float*)d_in[10];
    const float* A_B     = (const float*)d_in[11];
    const float* A_C     = (const float*)d_in[12];
    const float* x_tar   = (const float*)d_in[13];
    float* out = (float*)d_out;

    cudaFuncSetAttribute(fc1_kernel, cudaFuncAttributeMaxDynamicSharedMemorySize,
                         FC1SMEM);
    cudaFuncSetAttribute(moe_kernel, cudaFuncAttributeMaxDynamicSharedMemorySize,
                         SMEMC);

    conv1_kernel<<<N_CLASSES * 5, 512>>>(images, conv1_w, conv1_b, fc1_w, fc2_w);
    conv2_kernel<<<N_CLASSES * 10, 256>>>(conv2_w, conv2_b);
    fc1_kernel<<<128, 256, FC1SMEM>>>(fc1_w, fc1_b);
    moe_kernel<<<BATCH / TS, 1024, SMEMC>>>(x, cls, fc2_b, A_B, A_C, x_tar, out);
    (void)in_sizes; (void)n_in; (void)out_size;
}

// round 12
// speedup vs baseline: 1.2828x; 1.2828x over previous
#include <cuda_runtime.h>
#include <cuda_bf16.h>
#include <cstdint>

#define N_CLASSES 26
#define IMG 68
#define BATCH 8192
#define NEXP 64
#define FC1N 500
#define FLATN 1960

// scratch (device globals; no allocation allowed; zero-initialized)
__device__ __align__(16) float g_p1[N_CLASSES * 5 * 32 * 32];
__device__ __align__(16) float g_hcls[N_CLASSES * FLATN];
__device__ __align__(16) float g_u[N_CLASSES * 512];          // k-padded to 512
__device__ __align__(16) float2 g_wx[512];                    // k-padded
// bf16 split of fc2_w: [part hi/lo][64 experts][536 k-padded row]
__device__ __align__(16) __nv_bfloat16 g_wbf[2 * 64 * 536];

// ---------------------------------------------------------------------------
// mma / ldmatrix helpers (sm_80+ family-portable; NO tcgen05)
// ---------------------------------------------------------------------------
__device__ __forceinline__ uint32_t smem_to_u32(const void* p) {
    uint32_t a;
    asm("{ .reg .u64 t; cvta.to.shared.u64 t, %1; cvt.u32.u64 %0, t; }"
        : "=r"(a) : "l"(p));
    return a;
}
__device__ __forceinline__ void ldm_x4(uint32_t& r0, uint32_t& r1,
                                       uint32_t& r2, uint32_t& r3, uint32_t addr) {
    asm volatile("ldmatrix.sync.aligned.m8n8.x4.shared.b16 {%0,%1,%2,%3}, [%4];"
                 : "=r"(r0), "=r"(r1), "=r"(r2), "=r"(r3) : "r"(addr));
}
__device__ __forceinline__ void mma16816(float* c, const uint32_t* a,
                                         uint32_t b0, uint32_t b1) {
    asm volatile(
        "mma.sync.aligned.m16n8k16.row.col.f32.bf16.bf16.f32 "
        "{%0,%1,%2,%3}, {%4,%5,%6,%7}, {%8,%9}, {%0,%1,%2,%3};"
        : "+f"(c[0]), "+f"(c[1]), "+f"(c[2]), "+f"(c[3])
        : "r"(a[0]), "r"(a[1]), "r"(a[2]), "r"(a[3]), "r"(b0), "r"(b1));
}

// ---------------------------------------------------------------------------
// Kernel A1: conv1 + relu + maxpool2. Side work: build g_wbf (bf16 split of
// fc2_w, [part][e][536]) and zero-padded g_wx. grid = 130, block = 512.
// ---------------------------------------------------------------------------
__global__ void conv1_kernel(const float* __restrict__ images,
                             const float* __restrict__ w1,
                             const float* __restrict__ b1,
                             const float* __restrict__ fc1_w,
                             const float* __restrict__ fc2_w) {
    __shared__ float s_img[IMG * IMG];
    __shared__ float s_w[25];
    int c = blockIdx.x / 5, ch = blockIdx.x % 5;
    int tid = threadIdx.x;

    int gt = blockIdx.x * 512 + tid;
    if (gt < 65536) {
        int part = gt >> 15, r = gt & 32767;
        int e = r >> 9, k = r & 511;
        float val = (k < FC1N) ? fc2_w[e * FC1N + k] : 0.f;
        __nv_bfloat16 hi = __float2bfloat16(val);
        __nv_bfloat16 res = __float2bfloat16(val - __bfloat162float(hi));
        g_wbf[part * (64 * 536) + e * 536 + k] = part ? res : hi;
    }
    if (gt < 512) {
        float2 v = make_float2(0.f, 0.f);
        if (gt < FC1N) {
            v.x = fc1_w[gt * 1962 + 1960];
            v.y = fc1_w[gt * 1962 + 1961];
        }
        g_wx[gt] = v;
    }

    const float* img = images + c * IMG * IMG;
    for (int i = tid; i < IMG * IMG; i += 512) s_img[i] = img[i];
    if (tid < 25) s_w[tid] = w1[ch * 25 + tid];
    __syncthreads();
    float bb = b1[ch];
    float wr[25];
#pragma unroll
    for (int i = 0; i < 25; i++) wr[i] = s_w[i];
    float* outp = g_p1 + (c * 5 + ch) * 1024;
    for (int i = tid; i < 1024; i += 512) {
        int oy = i >> 5, ox = i & 31;
        int y0 = 2 * oy, x0 = 2 * ox;
        float p[6][6];
#pragma unroll
        for (int r = 0; r < 6; r++)
#pragma unroll
            for (int cc = 0; cc < 6; cc++) p[r][cc] = s_img[(y0 + r) * IMG + x0 + cc];
        float a00 = bb, a01 = bb, a10 = bb, a11 = bb;
#pragma unroll
        for (int ky = 0; ky < 5; ky++)
#pragma unroll
            for (int kx = 0; kx < 5; kx++) {
                float w = wr[ky * 5 + kx];
                a00 = fmaf(p[ky][kx], w, a00);
                a01 = fmaf(p[ky][kx + 1], w, a01);
                a10 = fmaf(p[ky + 1][kx], w, a10);
                a11 = fmaf(p[ky + 1][kx + 1], w, a11);
            }
        outp[i] = fmaxf(fmaxf(fmaxf(a00, a01), fmaxf(a10, a11)), 0.f);
    }
}

// ---------------------------------------------------------------------------
// Kernel A2: conv2 + relu + maxpool2. grid = 260, block = 256. (unchanged)
// ---------------------------------------------------------------------------
__global__ void conv2_kernel(const float* __restrict__ w2,
                             const float* __restrict__ b2) {
    __shared__ float s_p1[5 * 1024];
    __shared__ float s_w[125];
    int c = blockIdx.x / 10, co = blockIdx.x % 10;
    int tid = threadIdx.x;
    for (int i = tid; i < 5120; i += 256) s_p1[i] = g_p1[c * 5120 + i];
    if (tid < 125) s_w[tid] = w2[co * 125 + tid];
    __syncthreads();
    float bb = b2[co];
    for (int i = tid; i < 196; i += 256) {
        int oy = i / 14, ox = i % 14;
        int y0 = 2 * oy, x0 = 2 * ox;
        float a00 = bb, a01 = bb, a10 = bb, a11 = bb;
#pragma unroll
        for (int ci = 0; ci < 5; ci++) {
            const float* base = s_p1 + ci * 1024 + y0 * 32 + x0;
            float p[6][6];
#pragma unroll
            for (int r = 0; r < 6; r++)
#pragma unroll
                for (int cc = 0; cc < 6; cc++) p[r][cc] = base[r * 32 + cc];
            const float* wb = s_w + ci * 25;
#pragma unroll
            for (int ky = 0; ky < 5; ky++)
#pragma unroll
                for (int kx = 0; kx < 5; kx++) {
                    float w = wb[ky * 5 + kx];
                    a00 = fmaf(p[ky][kx], w, a00);
                    a01 = fmaf(p[ky][kx + 1], w, a01);
                    a10 = fmaf(p[ky + 1][kx], w, a10);
                    a11 = fmaf(p[ky + 1][kx + 1], w, a11);
                }
        }
        g_hcls[c * FLATN + co * 196 + i] =
            fmaxf(fmaxf(fmaxf(a00, a01), fmaxf(a10, a11)), 0.f);
    }
}

// ---------------------------------------------------------------------------
// Kernel B: fc1. grid = 128, block = 256. Writes g_u stride-512 + zero pad.
// ---------------------------------------------------------------------------
#define WROWP 1964
#define FC1SMEM ((16 * WROWP + 8 * WROWP + 1024) * 4)
__global__ void __launch_bounds__(256, 1) fc1_kernel(const float* __restrict__ fc1_w,
                                                     const float* __restrict__ fc1_b) {
    extern __shared__ float sm[];
    float* smW = sm;
    float* smH = smW + 16 * WROWP;
    float* pbuf = smH + 8 * WROWP;
    int tid = threadIdx.x;
    int ot = blockIdx.x & 31, ct = blockIdx.x >> 5;

    for (int idx = tid; idx < 16 * 980; idx += 256) {
        int r = idx / 980, k2 = idx - r * 980;
        int row = ot * 16 + r;
        float2 v = (row < FC1N)
                       ? ((const float2*)(fc1_w + (long)row * 1962))[k2]
                       : make_float2(0.f, 0.f);
        *(float2*)(smW + r * WROWP + 2 * k2) = v;
    }
    for (int idx = tid; idx < 8 * 490; idx += 256) {
        int r = idx / 490, q = idx - r * 490;
        int ci = ct * 8 + r;
        float4 v = (ci < N_CLASSES)
                       ? ((const float4*)(g_hcls + ci * FLATN))[q]
                       : make_float4(0.f, 0.f, 0.f, 0.f);
        *(float4*)(smH + r * WROWP + 4 * q) = v;
    }
    __syncthreads();

    int o = tid & 15, cg = (tid >> 4) & 1, kq8 = tid >> 5;
    const float4* wq = (const float4*)(smW + o * WROWP);
    const float4* h0 = (const float4*)(smH + (4 * cg + 0) * WROWP);
    const float4* h1 = (const float4*)(smH + (4 * cg + 1) * WROWP);
    const float4* h2 = (const float4*)(smH + (4 * cg + 2) * WROWP);
    const float4* h3 = (const float4*)(smH + (4 * cg + 3) * WROWP);
    float a0 = 0.f, a1 = 0.f, a2 = 0.f, a3 = 0.f;
    for (int q = kq8; q < 490; q += 8) {
        float4 w = wq[q];
        float4 v0 = h0[q], v1 = h1[q], v2 = h2[q], v3 = h3[q];
        a0 = fmaf(w.x, v0.x, a0); a0 = fmaf(w.y, v0.y, a0);
        a0 = fmaf(w.z, v0.z, a0); a0 = fmaf(w.w, v0.w, a0);
        a1 = fmaf(w.x, v1.x, a1); a1 = fmaf(w.y, v1.y, a1);
        a1 = fmaf(w.z, v1.z, a1); a1 = fmaf(w.w, v1.w, a1);
        a2 = fmaf(w.x, v2.x, a2); a2 = fmaf(w.y, v2.y, a2);
        a2 = fmaf(w.z, v2.z, a2); a2 = fmaf(w.w, v2.w, a2);
        a3 = fmaf(w.x, v3.x, a3); a3 = fmaf(w.y, v3.y, a3);
        a3 = fmaf(w.z, v3.z, a3); a3 = fmaf(w.w, v3.w, a3);
    }
    pbuf[o + 16 * (4 * cg + 0) + 128 * kq8] = a0;
    pbuf[o + 16 * (4 * cg + 1) + 128 * kq8] = a1;
    pbuf[o + 16 * (4 * cg + 2) + 128 * kq8] = a2;
    pbuf[o + 16 * (4 * cg + 3) + 128 * kq8] = a3;
    __syncthreads();
    if (tid < 128) {
        int oo = tid & 15, cc = tid >> 4;
        float s = 0.f;
#pragma unroll
        for (int j = 0; j < 8; j++) s += pbuf[oo + 16 * cc + 128 * j];
        int cls = ct * 8 + cc;
        int outn = ot * 16 + oo;           // 0..511
        if (cls < N_CLASSES) {
            float val = 0.f;
            if (outn < FC1N) val = s + fc1_b[outn];
            g_u[cls * 512 + outn] = val;   // pad 500..511 gets 0
        }
    }
}

// ---------------------------------------------------------------------------
// Kernel C: HMMA MoE. grid = 128 (64 samples each), block = 512 (16 warps).
// logits[64,64] = A[64,512] @ B[64,512]^T via mma.sync m16n8k16 bf16,
// 3-term split. Warp (w&3, w>>2) owns 16s x 16e tile. B resident in smem
// (copied from g_wbf, stride 1072B: conflict-free ldmatrix). A staged per
// 128-k chunk (stride 272B: conflict-free).
// ---------------------------------------------------------------------------
#define LR 68
#define SM_B 20480
#define B_PART 68608        // 64*536*2 bytes
#define SM_A (SM_B + 2 * B_PART)     // 157696
#define A_PART 17408        // 64*136*2 bytes
#define SMEMC (SM_A + 2 * A_PART)    // 192512

__global__ void __launch_bounds__(512, 1)
moe_kernel(const float* __restrict__ x, const int* __restrict__ cls_idx,
           const float* __restrict__ fc2_b,
           const float* __restrict__ A_B, const float* __restrict__ A_C,
           const float* __restrict__ x_tar, float* __restrict__ out) {
    extern __shared__ char smem[];
    uint32_t smem_u32 = smem_to_u32(smem);
    float* misc = (float*)smem;
    float* Gs = misc;               // [64][4]
    float* b2s = misc + 256;        // [64]
    float* sx0 = misc + 320;
    float* sx1 = misc + 384;
    float* sd0 = misc + 448;
    float* sd1 = misc + 512;
    int* scls = (int*)(misc + 576); // [64]
    float* Ls = misc + 640;         // [64][68]

    int tid = threadIdx.x, lane = tid & 31, warp = tid >> 5;  // 16 warps
    int base = blockIdx.x * 64;

    if (tid < 256) Gs[tid] = A_B[tid] + A_C[tid];
    if (tid < 64) b2s[tid] = fc2_b[tid];
    if (tid < 64) {
        int s = base + tid;
        float x0v = x[2 * s], x1v = x[2 * s + 1];
        sx0[tid] = x0v; sx1[tid] = x1v;
        sd0[tid] = x_tar[0] - x0v;
        sd1[tid] = x_tar[1] - x1v;
        scls[tid] = cls_idx[s];
    }
    // copy B splits into smem (134 KB, coalesced float4)
    {
        const float4* src = (const float4*)g_wbf;
        float4* dst = (float4*)(smem + SM_B);
        for (int i = tid; i < 8576; i += 512) dst[i] = src[i];
    }
    __syncthreads();

    int m0 = (warp & 3) * 16;       // sample tile
    int n0 = (warp >> 2) * 16;      // expert tile
    float c0[4] = {0.f, 0.f, 0.f, 0.f};   // n-half 0
    float c1[4] = {0.f, 0.f, 0.f, 0.f};   // n-half 1

    // per-lane ldmatrix addresses
    uint32_t aRow = (uint32_t)(lane & 15);
    uint32_t aCol = (uint32_t)((lane >> 4) * 16);
    uint32_t aHiBase = smem_u32 + SM_A + (m0 + aRow) * 272 + aCol;
    uint32_t bRow = (uint32_t)(n0 + ((lane >> 4) << 3) + (lane & 7));
    uint32_t bCol = (uint32_t)(((lane >> 3) & 1) * 16);
    uint32_t bHiBase = smem_u32 + SM_B + bRow * 1072 + bCol;

    const float4* u4 = (const float4*)g_u;
    const float4* wx4 = (const float4*)g_wx;

    for (int c = 0; c < 4; c++) {
        if (c) __syncthreads();  // A buffer reuse
        // stage A chunk: warp covers samples warp, warp+16, +32, +48
#pragma unroll
        for (int j = 0; j < 4; j++) {
            int s = warp + 16 * j;
            int cls = scls[s];
            float xx0 = sx0[s], xx1 = sx1[s];
            float4 uv = u4[cls * 128 + c * 32 + lane];
            float4 w0 = wx4[c * 64 + 2 * lane];
            float4 w1 = wx4[c * 64 + 2 * lane + 1];
            float h0 = fmaxf(fmaf(xx0, w0.x, fmaf(xx1, w0.y, uv.x)), 0.f);
            float h1 = fmaxf(fmaf(xx0, w0.z, fmaf(xx1, w0.w, uv.y)), 0.f);
            float h2 = fmaxf(fmaf(xx0, w1.x, fmaf(xx1, w1.y, uv.z)), 0.f);
            float h3 = fmaxf(fmaf(xx0, w1.z, fmaf(xx1, w1.w, uv.w)), 0.f);
            __nv_bfloat16 b0 = __float2bfloat16(h0);
            __nv_bfloat16 b1 = __float2bfloat16(h1);
            __nv_bfloat16 b2 = __float2bfloat16(h2);
            __nv_bfloat16 b3 = __float2bfloat16(h3);
            __nv_bfloat16 l0 = __float2bfloat16(h0 - __bfloat162float(b0));
            __nv_bfloat16 l1 = __float2bfloat16(h1 - __bfloat162float(b1));
            __nv_bfloat16 l2 = __float2bfloat16(h2 - __bfloat162float(b2));
            __nv_bfloat16 l3 = __float2bfloat16(h3 - __bfloat162float(b3));
            __nv_bfloat162 hA(b0, b1), hB(b2, b3), lA(l0, l1), lB(l2, l3);
            uint2 hv, lv;
            hv.x = *(uint32_t*)&hA; hv.y = *(uint32_t*)&hB;
            lv.x = *(uint32_t*)&lA; lv.y = *(uint32_t*)&lB;
            char* pa = smem + SM_A + s * 272 + lane * 8;
            *(uint2*)pa = hv;
            *(uint2*)(pa + A_PART) = lv;
        }
        __syncthreads();

        uint32_t aHi = aHiBase;                  // + ks*32 per step
        uint32_t bHi = bHiBase + c * 256;        // chunk k-offset in B rows
#pragma unroll
        for (int ks = 0; ks < 8; ks++) {
            uint32_t ah[4], al[4], bh[4], bl[4];
            ldm_x4(ah[0], ah[1], ah[2], ah[3], aHi);
            ldm_x4(al[0], al[1], al[2], al[3], aHi + A_PART);
            ldm_x4(bh[0], bh[1], bh[2], bh[3], bHi);
            ldm_x4(bl[0], bl[1], bl[2], bl[3], bHi + B_PART);
            mma16816(c0, ah, bh[0], bh[1]);
            mma16816(c1, ah, bh[2], bh[3]);
            mma16816(c0, al, bh[0], bh[1]);
            mma16816(c1, al, bh[2], bh[3]);
            mma16816(c0, ah, bl[0], bl[1]);
            mma16816(c1, ah, bl[2], bl[3]);
            aHi += 32;
            bHi += 32;
        }
    }
    __syncthreads();  // Ls region writes below must not race chunk staging

    // scatter C to Ls: rows m0+(lane>>2), +8; cols n0+(lane&3)*2..+1, +8
    {
        int r0 = m0 + (lane >> 2);
        int cb = n0 + (lane & 3) * 2;
        Ls[r0 * LR + cb] = c0[0];
        Ls[r0 * LR + cb + 1] = c0[1];
        Ls[(r0 + 8) * LR + cb] = c0[2];
        Ls[(r0 + 8) * LR + cb + 1] = c0[3];
        Ls[r0 * LR + cb + 8] = c1[0];
        Ls[r0 * LR + cb + 9] = c1[1];
        Ls[(r0 + 8) * LR + cb + 8] = c1[2];
        Ls[(r0 + 8) * LR + cb + 9] = c1[3];
    }
    __syncthreads();

    // softmax over 64 + expert mix; warp-per-sample (4 rounds over 16 warps)
    for (int s = warp; s < 64; s += 16) {
        float l0 = Ls[s * LR + lane] + b2s[lane];
        float l1 = Ls[s * LR + 32 + lane] + b2s[32 + lane];
        float m = fmaxf(l0, l1);
#pragma unroll
        for (int off = 16; off; off >>= 1) m = fmaxf(m, __shfl_xor_sync(~0u, m, off));
        float ee0 = __expf(l0 - m), ee1 = __expf(l1 - m);
        float d0 = sd0[s], d1 = sd1[s];
        const float* G0 = Gs + lane * 4;
        const float* G1 = Gs + (lane + 32) * 4;
        float y0 = ee0 * (G0[0] * d0 + G0[1] * d1) + ee1 * (G1[0] * d0 + G1[1] * d1);
        float y1 = ee0 * (G0[2] * d0 + G0[3] * d1) + ee1 * (G1[2] * d0 + G1[3] * d1);
        float Z = ee0 + ee1;
#pragma unroll
        for (int off = 16; off; off >>= 1) {
            y0 += __shfl_xor_sync(~0u, y0, off);
            y1 += __shfl_xor_sync(~0u, y1, off);
            Z += __shfl_xor_sync(~0u, Z, off);
        }
        if (lane == 0) {
            float inv = 1.f / Z;
            out[2 * (base + s) + 0] = y0 * inv;
            out[2 * (base + s) + 1] = y1 * inv;
        }
    }
}

// ---------------------------------------------------------------------------
extern "C" void kernel_launch(void* const* d_in, const int* in_sizes, int n_in,
                              void* d_out, int out_size) {
    const float* x       = (const float*)d_in[0];
    const int*   cls     = (const int*)d_in[1];
    const float* images  = (const float*)d_in[2];
    const float* conv1_w = (const float*)d_in[3];
    const float* conv1_b = (const float*)d_in[4];
    const float* conv2_w = (const float*)d_in[5];
    const float* conv2_b = (const float*)d_in[6];
    const float* fc1_w   = (const float*)d_in[7];
    const float* fc1_b   = (const float*)d_in[8];
    const float* fc2_w   = (const float*)d_in[9];
    const float* fc2_b   = (const float*)d_in[10];
    const float* A_B     = (const float*)d_in[11];
    const float* A_C     = (const float*)d_in[12];
    const float* x_tar   = (const float*)d_in[13];
    float* out = (float*)d_out;

    cudaFuncSetAttribute(fc1_kernel, cudaFuncAttributeMaxDynamicSharedMemorySize,
                         FC1SMEM);
    cudaFuncSetAttribute(moe_kernel, cudaFuncAttributeMaxDynamicSharedMemorySize,
                         SMEMC);

    conv1_kernel<<<N_CLASSES * 5, 512>>>(images, conv1_w, conv1_b, fc1_w, fc2_w);
    conv2_kernel<<<N_CLASSES * 10, 256>>>(conv2_w, conv2_b);
    fc1_kernel<<<128, 256, FC1SMEM>>>(fc1_w, fc1_b);
    moe_kernel<<<BATCH / 64, 512, SMEMC>>>(x, cls, fc2_b, A_B, A_C, x_tar, out);
    (void)in_sizes; (void)n_in; (void)out_size;
}

// round 13
// speedup vs baseline: 1.5576x; 1.2143x over previous
#include <cuda_runtime.h>
#include <cuda_bf16.h>
#include <cstdint>

#define N_CLASSES 26
#define IMG 68
#define BATCH 8192
#define NEXP 64
#define FC1N 500
#define FLATN 1960

// scratch (device globals; no allocation allowed)
__device__ __align__(16) float g_p1[N_CLASSES * 5 * 32 * 32];
__device__ __align__(16) float g_hcls[N_CLASSES * FLATN];
__device__ __align__(16) float g_u[N_CLASSES * 512];          // k-padded to 512
__device__ __align__(16) float2 g_wx[512];                    // k-padded
// bf16 split of fc2_w, chunked: [chunk 0..3][part hi/lo][64 e][136]
__device__ __align__(16) __nv_bfloat16 g_wbf[4 * 2 * 64 * 136];

// ---------------------------------------------------------------------------
// mma / ldmatrix / cp.async helpers (sm_80+ family-portable)
// ---------------------------------------------------------------------------
__device__ __forceinline__ uint32_t smem_to_u32(const void* p) {
    uint32_t a;
    asm("{ .reg .u64 t; cvta.to.shared.u64 t, %1; cvt.u32.u64 %0, t; }"
        : "=r"(a) : "l"(p));
    return a;
}
__device__ __forceinline__ void ldm_x4(uint32_t& r0, uint32_t& r1,
                                       uint32_t& r2, uint32_t& r3, uint32_t addr) {
    asm volatile("ldmatrix.sync.aligned.m8n8.x4.shared.b16 {%0,%1,%2,%3}, [%4];"
                 : "=r"(r0), "=r"(r1), "=r"(r2), "=r"(r3) : "r"(addr));
}
__device__ __forceinline__ void mma16816(float* c, const uint32_t* a,
                                         uint32_t b0, uint32_t b1) {
    asm volatile(
        "mma.sync.aligned.m16n8k16.row.col.f32.bf16.bf16.f32 "
        "{%0,%1,%2,%3}, {%4,%5,%6,%7}, {%8,%9}, {%0,%1,%2,%3};"
        : "+f"(c[0]), "+f"(c[1]), "+f"(c[2]), "+f"(c[3])
        : "r"(a[0]), "r"(a[1]), "r"(a[2]), "r"(a[3]), "r"(b0), "r"(b1));
}
#define CP_ASYNC16(dst, src) \
    asm volatile("cp.async.cg.shared.global [%0], [%1], 16;" \
                 :: "r"(dst), "l"(src) : "memory")
#define CP_COMMIT() asm volatile("cp.async.commit_group;" ::: "memory")

// ---------------------------------------------------------------------------
// Kernel A1: conv1 + relu + maxpool2. Side work: build chunked g_wbf and
// zero-padded g_wx. grid = 130, block = 512.
// ---------------------------------------------------------------------------
__global__ void conv1_kernel(const float* __restrict__ images,
                             const float* __restrict__ w1,
                             const float* __restrict__ b1,
                             const float* __restrict__ fc1_w,
                             const float* __restrict__ fc2_w) {
    __shared__ float s_img[IMG * IMG];
    __shared__ float s_w[25];
    int c = blockIdx.x / 5, ch = blockIdx.x % 5;
    int tid = threadIdx.x;

    int gt = blockIdx.x * 512 + tid;
    if (gt < 65536) {
        int cch = gt >> 14;          // chunk 0..3
        int part = (gt >> 13) & 1;   // hi/lo
        int e = (gt >> 7) & 63;
        int kk = gt & 127;
        int k = cch * 128 + kk;
        float val = (k < FC1N) ? fc2_w[e * FC1N + k] : 0.f;
        __nv_bfloat16 hi = __float2bfloat16(val);
        __nv_bfloat16 res = __float2bfloat16(val - __bfloat162float(hi));
        g_wbf[((cch * 2 + part) * 64 + e) * 136 + kk] = part ? res : hi;
    }
    if (gt < 512) {
        float2 v = make_float2(0.f, 0.f);
        if (gt < FC1N) {
            v.x = fc1_w[gt * 1962 + 1960];
            v.y = fc1_w[gt * 1962 + 1961];
        }
        g_wx[gt] = v;
    }

    const float* img = images + c * IMG * IMG;
    for (int i = tid; i < IMG * IMG; i += 512) s_img[i] = img[i];
    if (tid < 25) s_w[tid] = w1[ch * 25 + tid];
    __syncthreads();
    float bb = b1[ch];
    float wr[25];
#pragma unroll
    for (int i = 0; i < 25; i++) wr[i] = s_w[i];
    float* outp = g_p1 + (c * 5 + ch) * 1024;
    for (int i = tid; i < 1024; i += 512) {
        int oy = i >> 5, ox = i & 31;
        int y0 = 2 * oy, x0 = 2 * ox;
        float p[6][6];
#pragma unroll
        for (int r = 0; r < 6; r++)
#pragma unroll
            for (int cc = 0; cc < 6; cc++) p[r][cc] = s_img[(y0 + r) * IMG + x0 + cc];
        float a00 = bb, a01 = bb, a10 = bb, a11 = bb;
#pragma unroll
        for (int ky = 0; ky < 5; ky++)
#pragma unroll
            for (int kx = 0; kx < 5; kx++) {
                float w = wr[ky * 5 + kx];
                a00 = fmaf(p[ky][kx], w, a00);
                a01 = fmaf(p[ky][kx + 1], w, a01);
                a10 = fmaf(p[ky + 1][kx], w, a10);
                a11 = fmaf(p[ky + 1][kx + 1], w, a11);
            }
        outp[i] = fmaxf(fmaxf(fmaxf(a00, a01), fmaxf(a10, a11)), 0.f);
    }
}

// ---------------------------------------------------------------------------
// Kernel A2: conv2 + relu + maxpool2. grid = 260, block = 256. (unchanged)
// ---------------------------------------------------------------------------
__global__ void conv2_kernel(const float* __restrict__ w2,
                             const float* __restrict__ b2) {
    __shared__ float s_p1[5 * 1024];
    __shared__ float s_w[125];
    int c = blockIdx.x / 10, co = blockIdx.x % 10;
    int tid = threadIdx.x;
    for (int i = tid; i < 5120; i += 256) s_p1[i] = g_p1[c * 5120 + i];
    if (tid < 125) s_w[tid] = w2[co * 125 + tid];
    __syncthreads();
    float bb = b2[co];
    for (int i = tid; i < 196; i += 256) {
        int oy = i / 14, ox = i % 14;
        int y0 = 2 * oy, x0 = 2 * ox;
        float a00 = bb, a01 = bb, a10 = bb, a11 = bb;
#pragma unroll
        for (int ci = 0; ci < 5; ci++) {
            const float* base = s_p1 + ci * 1024 + y0 * 32 + x0;
            float p[6][6];
#pragma unroll
            for (int r = 0; r < 6; r++)
#pragma unroll
                for (int cc = 0; cc < 6; cc++) p[r][cc] = base[r * 32 + cc];
            const float* wb = s_w + ci * 25;
#pragma unroll
            for (int ky = 0; ky < 5; ky++)
#pragma unroll
                for (int kx = 0; kx < 5; kx++) {
                    float w = wb[ky * 5 + kx];
                    a00 = fmaf(p[ky][kx], w, a00);
                    a01 = fmaf(p[ky][kx + 1], w, a01);
                    a10 = fmaf(p[ky + 1][kx], w, a10);
                    a11 = fmaf(p[ky + 1][kx + 1], w, a11);
                }
        }
        g_hcls[c * FLATN + co * 196 + i] =
            fmaxf(fmaxf(fmaxf(a00, a01), fmaxf(a10, a11)), 0.f);
    }
}

// ---------------------------------------------------------------------------
// Kernel B: fc1. grid = 128, block = 512 (16 k-slabs -> halved serial loop).
// Writes g_u stride-512 + zero pad.
// ---------------------------------------------------------------------------
#define WROWP 1964
#define FC1SMEM ((16 * WROWP + 8 * WROWP + 2048) * 4)
__global__ void __launch_bounds__(512, 1) fc1_kernel(const float* __restrict__ fc1_w,
                                                     const float* __restrict__ fc1_b) {
    extern __shared__ float sm[];
    float* smW = sm;                    // [16][1964]
    float* smH = smW + 16 * WROWP;      // [8][1964]
    float* pbuf = smH + 8 * WROWP;      // [2048]
    int tid = threadIdx.x;
    int ot = blockIdx.x & 31, ct = blockIdx.x >> 5;

    for (int idx = tid; idx < 16 * 980; idx += 512) {
        int r = idx / 980, k2 = idx - r * 980;
        int row = ot * 16 + r;
        float2 v = (row < FC1N)
                       ? ((const float2*)(fc1_w + (long)row * 1962))[k2]
                       : make_float2(0.f, 0.f);
        *(float2*)(smW + r * WROWP + 2 * k2) = v;
    }
    for (int idx = tid; idx < 8 * 490; idx += 512) {
        int r = idx / 490, q = idx - r * 490;
        int ci = ct * 8 + r;
        float4 v = (ci < N_CLASSES)
                       ? ((const float4*)(g_hcls + ci * FLATN))[q]
                       : make_float4(0.f, 0.f, 0.f, 0.f);
        *(float4*)(smH + r * WROWP + 4 * q) = v;
    }
    __syncthreads();

    int o = tid & 15, cg = (tid >> 4) & 1, kq = tid >> 5;  // kq 0..15
    const float4* wq = (const float4*)(smW + o * WROWP);
    const float4* h0 = (const float4*)(smH + (4 * cg + 0) * WROWP);
    const float4* h1 = (const float4*)(smH + (4 * cg + 1) * WROWP);
    const float4* h2 = (const float4*)(smH + (4 * cg + 2) * WROWP);
    const float4* h3 = (const float4*)(smH + (4 * cg + 3) * WROWP);
    float a0 = 0.f, a1 = 0.f, a2 = 0.f, a3 = 0.f;
    for (int q = kq; q < 490; q += 16) {
        float4 w = wq[q];
        float4 v0 = h0[q], v1 = h1[q], v2 = h2[q], v3 = h3[q];
        a0 = fmaf(w.x, v0.x, a0); a0 = fmaf(w.y, v0.y, a0);
        a0 = fmaf(w.z, v0.z, a0); a0 = fmaf(w.w, v0.w, a0);
        a1 = fmaf(w.x, v1.x, a1); a1 = fmaf(w.y, v1.y, a1);
        a1 = fmaf(w.z, v1.z, a1); a1 = fmaf(w.w, v1.w, a1);
        a2 = fmaf(w.x, v2.x, a2); a2 = fmaf(w.y, v2.y, a2);
        a2 = fmaf(w.z, v2.z, a2); a2 = fmaf(w.w, v2.w, a2);
        a3 = fmaf(w.x, v3.x, a3); a3 = fmaf(w.y, v3.y, a3);
        a3 = fmaf(w.z, v3.z, a3); a3 = fmaf(w.w, v3.w, a3);
    }
    pbuf[o + 16 * (4 * cg + 0) + 128 * kq] = a0;
    pbuf[o + 16 * (4 * cg + 1) + 128 * kq] = a1;
    pbuf[o + 16 * (4 * cg + 2) + 128 * kq] = a2;
    pbuf[o + 16 * (4 * cg + 3) + 128 * kq] = a3;
    __syncthreads();
    if (tid < 128) {
        int oo = tid & 15, cc = tid >> 4;
        float s = 0.f;
#pragma unroll
        for (int j = 0; j < 16; j++) s += pbuf[oo + 16 * cc + 128 * j];
        int cls = ct * 8 + cc;
        int outn = ot * 16 + oo;
        if (cls < N_CLASSES) {
            float val = 0.f;
            if (outn < FC1N) val = s + fc1_b[outn];
            g_u[cls * 512 + outn] = val;
        }
    }
}

// ---------------------------------------------------------------------------
// Kernel C: HMMA MoE. grid = 256 (32 samples each), block = 256 (8 warps).
// smem 87 KB -> 2 blocks/SM. B staged per 128-k chunk, DOUBLE-BUFFERED via
// cp.async (prefetch chunk c+1 overlaps A-staging + mma of chunk c).
// Warp (w&1, w>>1) owns 16s x 16e tile. 3-term bf16 split.
// ---------------------------------------------------------------------------
#define LR 68
#define SM_B 2048
#define BCH 34816           // bytes per B chunk (2 parts x 64 x 136 bf16)
#define B_PARTB 17408
#define SM_A (SM_B + 2 * BCH)      // 71680
#define A_PARTB 8704        // 32*136*2
#define SMEMC (SM_A + 2 * A_PARTB) // 89088

__global__ void __launch_bounds__(256, 2)
moe_kernel(const float* __restrict__ x, const int* __restrict__ cls_idx,
           const float* __restrict__ fc2_b,
           const float* __restrict__ A_B, const float* __restrict__ A_C,
           const float* __restrict__ x_tar, float* __restrict__ out) {
    extern __shared__ char smem[];
    uint32_t smem_u32 = smem_to_u32(smem);
    float* misc = (float*)smem;
    float* Gs = misc;               // [64][4]
    float* b2s = misc + 256;        // [64]
    float* sx0 = misc + 320;        // [32]
    float* sx1 = misc + 352;
    float* sd0 = misc + 384;
    float* sd1 = misc + 416;
    int* scls = (int*)(misc + 448); // [32]
    float* Ls = (float*)(smem + SM_A);  // [32][68], aliases A after mainloop

    int tid = threadIdx.x, lane = tid & 31, warp = tid >> 5;  // 8 warps
    int base = blockIdx.x * 32;

    if (tid < 256) Gs[tid] = A_B[tid] + A_C[tid];
    if (tid >= 64 && tid < 128) b2s[tid - 64] = fc2_b[tid - 64];
    if (tid < 32) {
        int s = base + tid;
        float x0v = x[2 * s], x1v = x[2 * s + 1];
        sx0[tid] = x0v; sx1[tid] = x1v;
        sd0[tid] = x_tar[0] - x0v;
        sd1[tid] = x_tar[1] - x1v;
        scls[tid] = cls_idx[s];
    }

    // prologue: prefetch B chunk 0 into buffer 0
    {
        const char* src = (const char*)g_wbf;
        uint32_t dst = smem_u32 + SM_B;
        for (int i = tid; i < 2176; i += 256)
            CP_ASYNC16(dst + i * 16, src + i * 16);
        CP_COMMIT();
    }
    __syncthreads();  // misc ready (scls/sx needed by staging)

    int m0 = (warp & 1) * 16;       // sample tile
    int n0 = (warp >> 1) * 16;      // expert tile
    float c0[4] = {0.f, 0.f, 0.f, 0.f};
    float c1[4] = {0.f, 0.f, 0.f, 0.f};

    uint32_t aRow = (uint32_t)(lane & 15);
    uint32_t aCol = (uint32_t)((lane >> 4) * 16);
    uint32_t aHiBase = smem_u32 + SM_A + (m0 + aRow) * 272 + aCol;
    uint32_t bRow = (uint32_t)(n0 + ((lane >> 4) << 3) + (lane & 7));
    uint32_t bCol = (uint32_t)(((lane >> 3) & 1) * 16);
    uint32_t bHiOff = bRow * 272 + bCol;

    const float4* u4 = (const float4*)g_u;
    const float4* wx4 = (const float4*)g_wx;

    for (int c = 0; c < 4; c++) {
        // prefetch next B chunk into the other buffer
        if (c < 3) {
            const char* src = (const char*)g_wbf + (c + 1) * BCH;
            uint32_t dst = smem_u32 + SM_B + ((c + 1) & 1) * BCH;
            for (int i = tid; i < 2176; i += 256)
                CP_ASYNC16(dst + i * 16, src + i * 16);
            CP_COMMIT();
        }
        // stage A chunk c: warp covers samples warp, warp+8, +16, +24
#pragma unroll
        for (int j = 0; j < 4; j++) {
            int s = warp + 8 * j;
            int cls = scls[s];
            float xx0 = sx0[s], xx1 = sx1[s];
            float4 uv = u4[cls * 128 + c * 32 + lane];
            float4 w0 = wx4[c * 64 + 2 * lane];
            float4 w1 = wx4[c * 64 + 2 * lane + 1];
            float h0 = fmaxf(fmaf(xx0, w0.x, fmaf(xx1, w0.y, uv.x)), 0.f);
            float h1 = fmaxf(fmaf(xx0, w0.z, fmaf(xx1, w0.w, uv.y)), 0.f);
            float h2 = fmaxf(fmaf(xx0, w1.x, fmaf(xx1, w1.y, uv.z)), 0.f);
            float h3 = fmaxf(fmaf(xx0, w1.z, fmaf(xx1, w1.w, uv.w)), 0.f);
            __nv_bfloat16 b0 = __float2bfloat16(h0);
            __nv_bfloat16 b1 = __float2bfloat16(h1);
            __nv_bfloat16 b2 = __float2bfloat16(h2);
            __nv_bfloat16 b3 = __float2bfloat16(h3);
            __nv_bfloat16 l0 = __float2bfloat16(h0 - __bfloat162float(b0));
            __nv_bfloat16 l1 = __float2bfloat16(h1 - __bfloat162float(b1));
            __nv_bfloat16 l2 = __float2bfloat16(h2 - __bfloat162float(b2));
            __nv_bfloat16 l3 = __float2bfloat16(h3 - __bfloat162float(b3));
            __nv_bfloat162 hA(b0, b1), hB(b2, b3), lA(l0, l1), lB(l2, l3);
            uint2 hv, lv;
            hv.x = *(uint32_t*)&hA; hv.y = *(uint32_t*)&hB;
            lv.x = *(uint32_t*)&lA; lv.y = *(uint32_t*)&lB;
            char* pa = smem + SM_A + s * 272 + lane * 8;
            *(uint2*)pa = hv;
            *(uint2*)(pa + A_PARTB) = lv;
        }
        // B chunk c must have landed
        if (c < 3) asm volatile("cp.async.wait_group 1;" ::: "memory");
        else       asm volatile("cp.async.wait_group 0;" ::: "memory");
        __syncthreads();

        uint32_t aHi = aHiBase;
        uint32_t bHi = smem_u32 + SM_B + (c & 1) * BCH + bHiOff;
#pragma unroll
        for (int ks = 0; ks < 8; ks++) {
            uint32_t ah[4], al[4], bh[4], bl[4];
            ldm_x4(ah[0], ah[1], ah[2], ah[3], aHi);
            ldm_x4(al[0], al[1], al[2], al[3], aHi + A_PARTB);
            ldm_x4(bh[0], bh[1], bh[2], bh[3], bHi);
            ldm_x4(bl[0], bl[1], bl[2], bl[3], bHi + B_PARTB);
            mma16816(c0, ah, bh[0], bh[1]);
            mma16816(c1, ah, bh[2], bh[3]);
            mma16816(c0, al, bh[0], bh[1]);
            mma16816(c1, al, bh[2], bh[3]);
            mma16816(c0, ah, bl[0], bl[1]);
            mma16816(c1, ah, bl[2], bl[3]);
            aHi += 32;
            bHi += 32;
        }
        __syncthreads();  // A buffer reuse next chunk / Ls alias after loop
    }

    // scatter C to Ls (aliases A region)
    {
        int r0 = m0 + (lane >> 2);
        int cb = n0 + (lane & 3) * 2;
        Ls[r0 * LR + cb] = c0[0];
        Ls[r0 * LR + cb + 1] = c0[1];
        Ls[(r0 + 8) * LR + cb] = c0[2];
        Ls[(r0 + 8) * LR + cb + 1] = c0[3];
        Ls[r0 * LR + cb + 8] = c1[0];
        Ls[r0 * LR + cb + 9] = c1[1];
        Ls[(r0 + 8) * LR + cb + 8] = c1[2];
        Ls[(r0 + 8) * LR + cb + 9] = c1[3];
    }
    __syncthreads();

    // softmax over 64 + expert mix; warp-per-sample (4 rounds over 8 warps)
    for (int s = warp; s < 32; s += 8) {
        float l0 = Ls[s * LR + lane] + b2s[lane];
        float l1 = Ls[s * LR + 32 + lane] + b2s[32 + lane];
        float m = fmaxf(l0, l1);
#pragma unroll
        for (int off = 16; off; off >>= 1) m = fmaxf(m, __shfl_xor_sync(~0u, m, off));
        float ee0 = __expf(l0 - m), ee1 = __expf(l1 - m);
        float d0 = sd0[s], d1 = sd1[s];
        const float* G0 = Gs + lane * 4;
        const float* G1 = Gs + (lane + 32) * 4;
        float y0 = ee0 * (G0[0] * d0 + G0[1] * d1) + ee1 * (G1[0] * d0 + G1[1] * d1);
        float y1 = ee0 * (G0[2] * d0 + G0[3] * d1) + ee1 * (G1[2] * d0 + G1[3] * d1);
        float Z = ee0 + ee1;
#pragma unroll
        for (int off = 16; off; off >>= 1) {
            y0 += __shfl_xor_sync(~0u, y0, off);
            y1 += __shfl_xor_sync(~0u, y1, off);
            Z += __shfl_xor_sync(~0u, Z, off);
        }
        if (lane == 0) {
            float inv = 1.f / Z;
            out[2 * (base + s) + 0] = y0 * inv;
            out[2 * (base + s) + 1] = y1 * inv;
        }
    }
}

// ---------------------------------------------------------------------------
extern "C" void kernel_launch(void* const* d_in, const int* in_sizes, int n_in,
                              void* d_out, int out_size) {
    const float* x       = (const float*)d_in[0];
    const int*   cls     = (const int*)d_in[1];
    const float* images  = (const float*)d_in[2];
    const float* conv1_w = (const float*)d_in[3];
    const float* conv1_b = (const float*)d_in[4];
    const float* conv2_w = (const float*)d_in[5];
    const float* conv2_b = (const float*)d_in[6];
    const float* fc1_w   = (const float*)d_in[7];
    const float* fc1_b   = (const float*)d_in[8];
    const float* fc2_w   = (const float*)d_in[9];
    const float* fc2_b   = (const float*)d_in[10];
    const float* A_B     = (const float*)d_in[11];
    const float* A_C     = (const float*)d_in[12];
    const float* x_tar   = (const float*)d_in[13];
    float* out = (float*)d_out;

    cudaFuncSetAttribute(fc1_kernel, cudaFuncAttributeMaxDynamicSharedMemorySize,
                         FC1SMEM);
    cudaFuncSetAttribute(moe_kernel, cudaFuncAttributeMaxDynamicSharedMemorySize,
                         SMEMC);

    conv1_kernel<<<N_CLASSES * 5, 512>>>(images, conv1_w, conv1_b, fc1_w, fc2_w);
    conv2_kernel<<<N_CLASSES * 10, 256>>>(conv2_w, conv2_b);
    fc1_kernel<<<128, 512, FC1SMEM>>>(fc1_w, fc1_b);
    moe_kernel<<<BATCH / 32, 256, SMEMC>>>(x, cls, fc2_b, A_B, A_C, x_tar, out);
    (void)in_sizes; (void)n_in; (void)out_size;
}